// round 6
// baseline (speedup 1.0000x reference)
#include <cuda_runtime.h>

#define Bn 8
#define Hn 512
#define Wn 512
#define HW (Hn*Wn)
#define NPIX (Bn*HW)
#define WPR 16                 // 32-px words per row
#define PW (NPIX/32)           // words per bit-plane = 65536
#define TR 16
#define HALO 7
#define RT (TR+2*HALO)         // 30 tile rows
#define ITEMS (RT*WPR)         // 480
#define NTH 512
#define NBLK (Bn*(Hn/TR))      // 256

// Bit-plane grid: planes 0-3 elem bits, 4-6 density bits, 7 grav, 8 fall
__device__ unsigned int g_bp[9 * PW];

// ---------------------------------------------------------------------------
// Compress: one thread = one 32-px word. 8x float4 loads per channel build a
// 32-bit mask; planes are pure ORs of channel masks. Stone gravity rule via
// word shifts of the above-row ch9 mask (zero-padded at absolute borders).
// ---------------------------------------------------------------------------
__device__ __forceinline__ unsigned mask8(const float4* __restrict__ p) {
    unsigned mm = 0;
#pragma unroll
    for (int k = 0; k < 8; k++) {
        float4 v = p[k];
        unsigned nib = (v.x > 0.5f ? 1u : 0u) | (v.y > 0.5f ? 2u : 0u)
                     | (v.z > 0.5f ? 4u : 0u) | (v.w > 0.5f ? 8u : 0u);
        mm |= nib << (4 * k);
    }
    return mm;
}

__global__ void __launch_bounds__(256) k_compress(
    const float* __restrict__ world, const float* __restrict__ rnd,
    unsigned int* __restrict__ bp)
{
    int t = blockIdx.x * 256 + threadIdx.x;      // word index, 65536 total
    int b   = t >> 13;                           // 8192 words per image
    int off = t & 8191;
    int h = off >> 4, wq = off & 15;
    const float* ib = world + (size_t)b * 20 * HW + (size_t)h * Wn + wq * 32;

    unsigned m1  = mask8((const float4*)(ib + (size_t)1  * HW));
    unsigned m2  = mask8((const float4*)(ib + (size_t)2  * HW));
    unsigned m3  = mask8((const float4*)(ib + (size_t)3  * HW));
    unsigned m4  = mask8((const float4*)(ib + (size_t)4  * HW));
    unsigned m5  = mask8((const float4*)(ib + (size_t)5  * HW));
    unsigned m6  = mask8((const float4*)(ib + (size_t)6  * HW));
    unsigned m7  = mask8((const float4*)(ib + (size_t)7  * HW));
    unsigned m8  = mask8((const float4*)(ib + (size_t)8  * HW));
    unsigned m9  = mask8((const float4*)(ib + (size_t)9  * HW));
    unsigned m10 = mask8((const float4*)(ib + (size_t)10 * HW));
    unsigned m11 = mask8((const float4*)(ib + (size_t)11 * HW));
    unsigned m12 = mask8((const float4*)(ib + (size_t)12 * HW));
    unsigned m13 = mask8((const float4*)(ib + (size_t)13 * HW));
    unsigned mf  = mask8((const float4*)(rnd + (size_t)b * HW + (size_t)h * Wn + wq * 32));

    unsigned L = 0, R = 0;                       // stone-above neighbor bits
    if (h > 0) {
        const float* p9 = world + (size_t)b * 20 * HW + (size_t)9 * HW
                        + (size_t)(h - 1) * Wn + wq * 32;
        unsigned ma = mask8((const float4*)p9);
        unsigned lp = (wq > 0  && p9[-1] > 0.5f) ? 1u : 0u;
        unsigned rp = (wq < 15 && p9[32] > 0.5f) ? 1u : 0u;
        L = (ma << 1) | lp;
        R = (ma >> 1) | (rp << 31);
    }

    unsigned u  = m1|m2|m3|m4|m5|m6|m7|m8|m9|m10|m11|m12|m13;
    unsigned m0 = ~u;
    unsigned e0 = m1|m3|m5|m7|m9|m11|m13;
    unsigned e1 = m2|m3|m6|m7|m10|m11;
    unsigned e2 = m4|m5|m6|m7|m12|m13;
    unsigned e3 = m8|m9|m10|m11|m12|m13;
    unsigned d0 = m0|m2|m9|m10|m12;              // den bit0 (den 1 or 3)
    unsigned d1 = m2|m3|m9|m10|m11|m12;          // den bit1 (den 2 or 3)
    unsigned d2 = m1|m5|m6|m8|m13;               // den bit2 (den 4)
    unsigned gv = m0|m2|m3|m4|m7|m10|m11|m12 | (m9 & ~(L & R));

    bp[0*PW + t] = e0;  bp[1*PW + t] = e1;
    bp[2*PW + t] = e2;  bp[3*PW + t] = e3;
    bp[4*PW + t] = d0;  bp[5*PW + t] = d1;
    bp[6*PW + t] = d2;  bp[7*PW + t] = gv;
    bp[8*PW + t] = mf;
}

// ---------------------------------------------------------------------------
// Bitwise helpers (32 pixels per op)
// ---------------------------------------------------------------------------
__device__ __forceinline__ unsigned eq_den(const unsigned* p, int D) {
    unsigned b0 = (D & 1) ? p[4] : ~p[4];
    unsigned b1 = (D & 2) ? p[5] : ~p[5];
    unsigned b2 = (D & 4) ? p[6] : ~p[6];
    return b0 & b1 & b2;
}
__device__ __forceinline__ unsigned lt_den(const unsigned* p, int D) {
    if (D == 1) return ~p[6] & ~p[5] & ~p[4];
    if (D == 2) return ~p[6] & ~p[5];
    return ~p[6] & ~(p[5] & p[4]);              // D == 3
}
__device__ __forceinline__ unsigned eq_elem4(
    unsigned p0, unsigned p1, unsigned p2, unsigned p3, int E)
{
    unsigned b0 = (E & 1) ? p0 : ~p0;
    unsigned b1 = (E & 2) ? p1 : ~p1;
    unsigned b2 = (E & 4) ? p2 : ~p2;
    unsigned b3 = (E & 8) ? p3 : ~p3;
    return b0 & b1 & b2 & b3;
}
__device__ __forceinline__ unsigned eq_elem(const unsigned* p, int E) {
    return eq_elem4(p[0], p[1], p[2], p[3], E);
}
__device__ __forceinline__ unsigned gt3(
    unsigned x2, unsigned x1, unsigned x0,
    unsigned y2, unsigned y1, unsigned y0)
{
    unsigned eq2 = ~(x2 ^ y2), eq1 = ~(x1 ^ y1);
    return (x2 & ~y2) | (eq2 & x1 & ~y1) | (eq2 & eq1 & x0 & ~y0);
}

__shared__ unsigned s_mov[2][8][ITEMS];
__shared__ unsigned s_fall[ITEMS];
__shared__ unsigned s_dg[ITEMS];

template <int D>
__device__ __forceinline__ void grav_pass(
    unsigned (*src)[ITEMS], unsigned (*dst)[ITEMS], int i, int c)
{
    int rw = i * WPR + c;
    int ra = rw - WPR, rb = rw + WPR;
    unsigned s[8], a[8], bb[8];
#pragma unroll
    for (int p = 0; p < 8; p++) { s[p] = src[p][rw]; a[p] = src[p][ra]; bb[p] = src[p][rb]; }
    unsigned bel = eq_den(s, D) & lt_den(bb, D) & s[7] & bb[7];
    unsigned abv = eq_den(a, D) & lt_den(s, D) & a[7] & s[7];
    unsigned keep = ~(bel | abv);
#pragma unroll
    for (int p = 0; p < 8; p++)
        dst[p][rw] = (bel & bb[p]) | (abv & a[p]) | (keep & s[p]);
    s_dg[rw] |= abv;
}

template <int E, int LEFT>
__device__ __forceinline__ void diag_pass(
    unsigned (*src)[ITEMS], unsigned (*dst)[ITEMS], int i, int c)
{
    int rw = i * WPR + c;
    int wm = (c - 1) & 15, wp = (c + 1) & 15;
    int ba = (i - 1) * WPR, bbr = (i + 1) * WPR;

    unsigned s[8], bl[8], ar[8];
#pragma unroll
    for (int p = 0; p < 8; p++) s[p] = src[p][rw];
    unsigned sd = s_dg[rw], sf = s_fall[rw];
    unsigned bl_dg, ar_dg, ar_f;
    if (LEFT) {
#pragma unroll
        for (int p = 0; p < 8; p++) {
            bl[p] = __funnelshift_l(src[p][bbr + wm], src[p][bbr + c], 1);
            ar[p] = __funnelshift_r(src[p][ba + c], src[p][ba + wp], 1);
        }
        bl_dg = __funnelshift_l(s_dg[bbr + wm], s_dg[bbr + c], 1);
        ar_dg = __funnelshift_r(s_dg[ba + c], s_dg[ba + wp], 1);
        ar_f  = __funnelshift_r(s_fall[ba + c], s_fall[ba + wp], 1);
    } else {
#pragma unroll
        for (int p = 0; p < 8; p++) {
            bl[p] = __funnelshift_r(src[p][bbr + c], src[p][bbr + wp], 1);
            ar[p] = __funnelshift_l(src[p][ba + wm], src[p][ba + c], 1);
        }
        bl_dg = __funnelshift_r(s_dg[bbr + c], s_dg[bbr + wp], 1);
        ar_dg = __funnelshift_l(s_dg[ba + wm], s_dg[ba + c], 1);
        ar_f  = __funnelshift_l(s_fall[ba + wm], s_fall[ba + c], 1);
    }
    unsigned ms  = LEFT ? sf : ~sf;
    unsigned mar = LEFT ? ar_f : ~ar_f;
    unsigned bbl = eq_elem(s, E) & ~bl_dg & ~sd & ms
                 & gt3(s[6], s[5], s[4], bl[6], bl[5], bl[4]) & s[7] & bl[7];
    unsigned bar = eq_elem(ar, E) & ~ar_dg & ~sd & mar
                 & gt3(ar[6], ar[5], ar[4], s[6], s[5], s[4]) & ar[7] & s[7];
    unsigned keep = ~(bbl | bar);
#pragma unroll
    for (int p = 0; p < 8; p++)
        dst[p][rw] = (bbl & bl[p]) | (bar & ar[p]) | (keep & s[p]);
}

// ---------------------------------------------------------------------------
// Fused sim (bit-sliced, shrinking ranges) + uint-pattern decompress
// ---------------------------------------------------------------------------
__global__ void __launch_bounds__(NTH, 3) k_sim(
    const unsigned int* __restrict__ bp, float* __restrict__ out)
{
    int tid = threadIdx.x;
    int b = blockIdx.x >> 5, chunk = blockIdx.x & 31;
    int r0 = chunk * TR;

    // Load 9 planes (with vertical wrap) into SMEM
#pragma unroll
    for (int p = 0; p < 9; p++) {
        const unsigned* pp = bp + (size_t)p * PW + (size_t)b * (Hn * WPR);
        for (int rw = tid; rw < ITEMS; rw += NTH) {
            int i = rw >> 4, wq = rw & 15;
            int gr = (r0 - HALO + i) & (Hn - 1);
            unsigned v = pp[gr * WPR + wq];
            if (p < 8) s_mov[0][p][rw] = v; else s_fall[rw] = v;
        }
    }
    for (int rw = tid; rw < ITEMS; rw += NTH) s_dg[rw] = 0;
    __syncthreads();

    // Pass k computes exactly rows [k, RT-k)
    int i = (tid >> 4), c = tid & 15;
    if (tid < (RT- 2)*WPR) grav_pass<1>(s_mov[0], s_mov[1], i + 1, c);  __syncthreads();
    if (tid < (RT- 4)*WPR) grav_pass<2>(s_mov[1], s_mov[0], i + 2, c);  __syncthreads();
    if (tid < (RT- 6)*WPR) grav_pass<3>(s_mov[0], s_mov[1], i + 3, c);  __syncthreads();
    if (tid < (RT- 8)*WPR) diag_pass<2 ,1>(s_mov[1], s_mov[0], i + 4, c); __syncthreads();
    if (tid < (RT-10)*WPR) diag_pass<2 ,0>(s_mov[0], s_mov[1], i + 5, c); __syncthreads();
    if (tid < (RT-12)*WPR) diag_pass<12,1>(s_mov[1], s_mov[0], i + 6, c); __syncthreads();
    if (tid < (RT-14)*WPR) diag_pass<12,0>(s_mov[0], s_mov[1], i + 7, c); __syncthreads();
    // final state in s_mov[1], valid rows [7, 23)

    // Decompress: thread = half a word (16 px). 256 words x 2 halves = 512.
    {
        int word = tid >> 1;
        int half = tid & 1;
        int ii = (word >> 4) + HALO;
        int wq = word & 15;
        int rw = ii * WPR + wq;
        unsigned p0 = s_mov[1][0][rw], p1 = s_mov[1][1][rw];
        unsigned p2 = s_mov[1][2][rw], p3 = s_mov[1][3][rw];
        unsigned p4 = s_mov[1][4][rw], p5 = s_mov[1][5][rw];
        unsigned p6 = s_mov[1][6][rw], p7 = s_mov[1][7][rw];
        int gh = r0 + ii - HALO;
        int kb = half * 16;
        unsigned* ob = reinterpret_cast<unsigned*>(out)
                     + (size_t)b * 20 * HW + (size_t)gh * Wn + wq * 32 + kb;
        const unsigned ONE = 0x3f800000u;
#pragma unroll
        for (int ch = 0; ch < 14; ch++) {
            unsigned mc = eq_elem4(p0, p1, p2, p3, ch);
            unsigned* op = ob + (size_t)ch * HW;
#pragma unroll
            for (int j = 0; j < 4; j++) {
                int kk = kb + j * 4;
                uint4 v;
                v.x = (mc >> (kk + 0)) & 1 ? ONE : 0u;
                v.y = (mc >> (kk + 1)) & 1 ? ONE : 0u;
                v.z = (mc >> (kk + 2)) & 1 ? ONE : 0u;
                v.w = (mc >> (kk + 3)) & 1 ? ONE : 0u;
                *reinterpret_cast<uint4*>(op + j * 4) = v;
            }
        }
        // density channel (values 0..4 as f32 bit patterns)
        {
            unsigned* op = ob + (size_t)14 * HW;
#pragma unroll
            for (int j = 0; j < 4; j++) {
                uint4 v;
#pragma unroll
                for (int q = 0; q < 4; q++) {
                    int kk = kb + j * 4 + q;
                    unsigned b0 = (p4 >> kk) & 1, b1 = (p5 >> kk) & 1, b2 = (p6 >> kk) & 1;
                    unsigned pat = b2 ? 0x40800000u
                                 : (b1 ? (b0 ? 0x40400000u : 0x40000000u)
                                       : (b0 ? 0x3f800000u : 0u));
                    (&v.x)[q] = pat;
                }
                *reinterpret_cast<uint4*>(op + j * 4) = v;
            }
        }
        // gravity channel
        {
            unsigned* op = ob + (size_t)15 * HW;
#pragma unroll
            for (int j = 0; j < 4; j++) {
                int kk = kb + j * 4;
                uint4 v;
                v.x = (p7 >> (kk + 0)) & 1 ? ONE : 0u;
                v.y = (p7 >> (kk + 1)) & 1 ? ONE : 0u;
                v.z = (p7 >> (kk + 2)) & 1 ? ONE : 0u;
                v.w = (p7 >> (kk + 3)) & 1 ? ONE : 0u;
                *reinterpret_cast<uint4*>(op + j * 4) = v;
            }
        }
        // zero channels 16..19
        uint4 z = make_uint4(0u, 0u, 0u, 0u);
#pragma unroll
        for (int ch = 16; ch < 20; ch++) {
            unsigned* op = ob + (size_t)ch * HW;
#pragma unroll
            for (int j = 0; j < 4; j++)
                *reinterpret_cast<uint4*>(op + j * 4) = z;
        }
    }
}

// ---------------------------------------------------------------------------
extern "C" void kernel_launch(void* const* d_in, const int* in_sizes, int n_in,
                              void* d_out, int out_size)
{
    int wi = 0, ri = 1;
    if (n_in >= 2 && in_sizes[0] < in_sizes[1]) { wi = 1; ri = 0; }
    const float* world = (const float*)d_in[wi];
    const float* rnd   = (const float*)d_in[ri];
    float* out = (float*)d_out;

    unsigned int* bp;
    cudaGetSymbolAddress((void**)&bp, g_bp);

    k_compress<<<PW / 256, 256>>>(world, rnd, bp);
    k_sim<<<NBLK, NTH>>>(bp, out);
}

// round 8
// speedup vs baseline: 1.5152x; 1.5152x over previous
#include <cuda_runtime.h>

#define Bn 8
#define Hn 512
#define Wn 512
#define HW (Hn*Wn)
#define NPIX (Bn*HW)
#define WPR 16                 // 32-px words per row
#define PW (NPIX/32)           // words per bit-plane = 65536
#define TR 16
#define HALO 7
#define RT (TR+2*HALO)         // 30 tile rows
#define ITEMS (RT*WPR)         // 480
#define NTH 512
#define NBLK (Bn*(Hn/TR))      // 256

// Bit-planes: 0-3 elem bits, 4-6 density bits, 7 grav, 8 fall
__device__ unsigned int g_bp [9 * PW];
__device__ unsigned int g_bp2[8 * PW];   // post-sim planes (no fall needed)

__host__ __device__ constexpr unsigned long long make_den_lut() {
    constexpr int d[16] = {1,4,3,2,0,4,4,0,4,3,3,2,3,4,0,0};
    unsigned long long v = 0;
    for (int i = 0; i < 16; i++) v |= (unsigned long long)d[i] << (3*i);
    return v;
}
constexpr unsigned long long DEN_LUT = make_den_lut();
#define GRV_LUT 0x1E9Du

__device__ __forceinline__ unsigned eq_elem4(
    unsigned p0, unsigned p1, unsigned p2, unsigned p3, int E)
{
    unsigned b0 = (E & 1) ? p0 : ~p0;
    unsigned b1 = (E & 2) ? p1 : ~p1;
    unsigned b2 = (E & 4) ? p2 : ~p2;
    unsigned b3 = (E & 8) ? p3 : ~p3;
    return b0 & b1 & b2 & b3;
}

// ---------------------------------------------------------------------------
// Compress: warp = 128 consecutive pixels (quarter row). Per word k, lane
// loads pixel ws+32k+lane (coalesced), 9 ballots build the plane words.
// Stone-gravity rule via word-shift of the above-row ch9 ballot mask with
// cross-word carries (zero-padded at absolute H/W borders).
// ---------------------------------------------------------------------------
__global__ void __launch_bounds__(256) k_compress(
    const float* __restrict__ world, const float* __restrict__ rnd,
    unsigned int* __restrict__ bp)
{
    int gt   = blockIdx.x * 256 + threadIdx.x;
    int gw   = gt >> 5;                       // warp id, 16384 total
    int lane = gt & 31;
    int pxb  = gw << 7;                       // 128 px per warp
    int b    = pxb >> 18;
    int off  = pxb & (HW - 1);
    int h    = off >> 9;
    int ws   = off & 511;                     // 0,128,256,384
    const float* row  = world + (size_t)b * 20 * HW + (size_t)h * Wn;
    const float* rrow = rnd   + (size_t)b * HW      + (size_t)h * Wn;
    const float* p9r  = world + (size_t)b * 20 * HW + (size_t)9 * HW
                      + (size_t)(h - 1) * Wn;   // only deref when h>0

    // above-row stone masks for all 4 words + edge carries
    unsigned m9a[4];
#pragma unroll
    for (int k = 0; k < 4; k++) {
        float a = (h > 0) ? p9r[ws + 32 * k + lane] : 0.f;
        m9a[k] = __ballot_sync(~0u, a > 0.5f);
    }
    unsigned cL = 0, cR = 0;                  // uniform broadcast loads
    if (h > 0 && ws > 0)        cL = (p9r[ws - 1]   > 0.5f) ? 1u : 0u;
    if (h > 0 && ws + 128 < Wn) cR = (p9r[ws + 128] > 0.5f) ? 1u : 0u;

#pragma unroll
    for (int k = 0; k < 4; k++) {
        int w = ws + 32 * k + lane;
        int e = 0;
#pragma unroll
        for (int c = 1; c < 14; c++)
            if (row[(size_t)c * HW + w] > 0.5f) e = c;
        int den = (int)((DEN_LUT >> (3 * e)) & 7);
        int gvt = (GRV_LUT >> e) & 1;
        float r = rrow[w];

        unsigned me0 = __ballot_sync(~0u, e & 1);
        unsigned me1 = __ballot_sync(~0u, e & 2);
        unsigned me2 = __ballot_sync(~0u, e & 4);
        unsigned me3 = __ballot_sync(~0u, e & 8);
        unsigned md0 = __ballot_sync(~0u, den & 1);
        unsigned md1 = __ballot_sync(~0u, den & 2);
        unsigned md2 = __ballot_sync(~0u, den & 4);
        unsigned mg  = __ballot_sync(~0u, gvt);
        unsigned mfa = __ballot_sync(~0u, r > 0.5f);

        unsigned stone = me0 & ~me1 & ~me2 & me3;     // e == 9
        unsigned lc = k ? (m9a[k - 1] >> 31) : cL;
        unsigned rc = (k < 3) ? (m9a[k + 1] & 1u) : cR;
        unsigned L = (m9a[k] << 1) | lc;
        unsigned R = (m9a[k] >> 1) | (rc << 31);
        unsigned gv = (mg & ~stone) | (stone & ~(L & R));

        unsigned v = me0;
        v = lane == 1 ? me1 : v;  v = lane == 2 ? me2 : v;
        v = lane == 3 ? me3 : v;  v = lane == 4 ? md0 : v;
        v = lane == 5 ? md1 : v;  v = lane == 6 ? md2 : v;
        v = lane == 7 ? gv  : v;  v = lane == 8 ? mfa : v;
        if (lane < 9) bp[lane * PW + gw * 4 + k] = v;
    }
}

// ---------------------------------------------------------------------------
// Bitwise pass helpers (32 pixels per op)
// ---------------------------------------------------------------------------
__device__ __forceinline__ unsigned eq_den(const unsigned* p, int D) {
    unsigned b0 = (D & 1) ? p[4] : ~p[4];
    unsigned b1 = (D & 2) ? p[5] : ~p[5];
    unsigned b2 = (D & 4) ? p[6] : ~p[6];
    return b0 & b1 & b2;
}
__device__ __forceinline__ unsigned lt_den(const unsigned* p, int D) {
    if (D == 1) return ~p[6] & ~p[5] & ~p[4];
    if (D == 2) return ~p[6] & ~p[5];
    return ~p[6] & ~(p[5] & p[4]);              // D == 3
}
__device__ __forceinline__ unsigned gt3(
    unsigned x2, unsigned x1, unsigned x0,
    unsigned y2, unsigned y1, unsigned y0)
{
    unsigned eq2 = ~(x2 ^ y2), eq1 = ~(x1 ^ y1);
    return (x2 & ~y2) | (eq2 & x1 & ~y1) | (eq2 & eq1 & x0 & ~y0);
}

__shared__ unsigned s_mov[2][8][ITEMS];
__shared__ unsigned s_fall[ITEMS];
__shared__ unsigned s_dg[ITEMS];

template <int D>
__device__ __forceinline__ void grav_pass(
    unsigned (*src)[ITEMS], unsigned (*dst)[ITEMS], int i, int c)
{
    int rw = i * WPR + c;
    int ra = rw - WPR, rb = rw + WPR;
    unsigned s[8], a[8], bb[8];
#pragma unroll
    for (int p = 0; p < 8; p++) { s[p] = src[p][rw]; a[p] = src[p][ra]; bb[p] = src[p][rb]; }
    unsigned bel = eq_den(s, D) & lt_den(bb, D) & s[7] & bb[7];
    unsigned abv = eq_den(a, D) & lt_den(s, D) & a[7] & s[7];
    unsigned keep = ~(bel | abv);
#pragma unroll
    for (int p = 0; p < 8; p++)
        dst[p][rw] = (bel & bb[p]) | (abv & a[p]) | (keep & s[p]);
    s_dg[rw] |= abv;
}

template <int E, int LEFT>
__device__ __forceinline__ void diag_pass(
    unsigned (*src)[ITEMS], unsigned (*dst)[ITEMS], int i, int c)
{
    int rw = i * WPR + c;
    int wm = (c - 1) & 15, wp = (c + 1) & 15;
    int ba = (i - 1) * WPR, bbr = (i + 1) * WPR;

    unsigned s[8], bl[8], ar[8];
#pragma unroll
    for (int p = 0; p < 8; p++) s[p] = src[p][rw];
    unsigned sd = s_dg[rw], sf = s_fall[rw];
    unsigned bl_dg, ar_dg, ar_f;
    if (LEFT) {
#pragma unroll
        for (int p = 0; p < 8; p++) {
            bl[p] = __funnelshift_l(src[p][bbr + wm], src[p][bbr + c], 1);
            ar[p] = __funnelshift_r(src[p][ba + c], src[p][ba + wp], 1);
        }
        bl_dg = __funnelshift_l(s_dg[bbr + wm], s_dg[bbr + c], 1);
        ar_dg = __funnelshift_r(s_dg[ba + c], s_dg[ba + wp], 1);
        ar_f  = __funnelshift_r(s_fall[ba + c], s_fall[ba + wp], 1);
    } else {
#pragma unroll
        for (int p = 0; p < 8; p++) {
            bl[p] = __funnelshift_r(src[p][bbr + c], src[p][bbr + wp], 1);
            ar[p] = __funnelshift_l(src[p][ba + wm], src[p][ba + c], 1);
        }
        bl_dg = __funnelshift_r(s_dg[bbr + c], s_dg[bbr + wp], 1);
        ar_dg = __funnelshift_l(s_dg[ba + wm], s_dg[ba + c], 1);
        ar_f  = __funnelshift_l(s_fall[ba + wm], s_fall[ba + c], 1);
    }
    unsigned ms  = LEFT ? sf : ~sf;
    unsigned mar = LEFT ? ar_f : ~ar_f;
    unsigned bbl = eq_elem4(s[0], s[1], s[2], s[3], E) & ~bl_dg & ~sd & ms
                 & gt3(s[6], s[5], s[4], bl[6], bl[5], bl[4]) & s[7] & bl[7];
    unsigned bar = eq_elem4(ar[0], ar[1], ar[2], ar[3], E) & ~ar_dg & ~sd & mar
                 & gt3(ar[6], ar[5], ar[4], s[6], s[5], s[4]) & ar[7] & s[7];
    unsigned keep = ~(bbl | bar);
#pragma unroll
    for (int p = 0; p < 8; p++)
        dst[p][rw] = (bbl & bl[p]) | (bar & ar[p]) | (keep & s[p]);
}

// ---------------------------------------------------------------------------
// Pass kernel: 7 bit-sliced passes in SMEM, write final planes to g_bp2.
// ---------------------------------------------------------------------------
__global__ void __launch_bounds__(NTH, 2) k_passes(
    const unsigned int* __restrict__ bp, unsigned int* __restrict__ bp2)
{
    int tid = threadIdx.x;
    int b = blockIdx.x >> 5, chunk = blockIdx.x & 31;
    int r0 = chunk * TR;

#pragma unroll
    for (int p = 0; p < 9; p++) {
        const unsigned* pp = bp + (size_t)p * PW + (size_t)b * (Hn * WPR);
        for (int rw = tid; rw < ITEMS; rw += NTH) {
            int i = rw >> 4, wq = rw & 15;
            int gr = (r0 - HALO + i) & (Hn - 1);
            unsigned v = pp[gr * WPR + wq];
            if (p < 8) s_mov[0][p][rw] = v; else s_fall[rw] = v;
        }
    }
    for (int rw = tid; rw < ITEMS; rw += NTH) s_dg[rw] = 0;
    __syncthreads();

    int i = (tid >> 4), c = tid & 15;
    if (tid < (RT- 2)*WPR) grav_pass<1>(s_mov[0], s_mov[1], i + 1, c);    __syncthreads();
    if (tid < (RT- 4)*WPR) grav_pass<2>(s_mov[1], s_mov[0], i + 2, c);    __syncthreads();
    if (tid < (RT- 6)*WPR) grav_pass<3>(s_mov[0], s_mov[1], i + 3, c);    __syncthreads();
    if (tid < (RT- 8)*WPR) diag_pass<2 ,1>(s_mov[1], s_mov[0], i + 4, c); __syncthreads();
    if (tid < (RT-10)*WPR) diag_pass<2 ,0>(s_mov[0], s_mov[1], i + 5, c); __syncthreads();
    if (tid < (RT-12)*WPR) diag_pass<12,1>(s_mov[1], s_mov[0], i + 6, c); __syncthreads();
    if (tid < (RT-14)*WPR) diag_pass<12,0>(s_mov[0], s_mov[1], i + 7, c); __syncthreads();
    // final state in s_mov[1], valid rows [HALO, HALO+TR)

    for (int idx = tid; idx < TR * WPR; idx += NTH) {
        int i2 = idx >> 4, wq = idx & 15;
        int rw = (i2 + HALO) * WPR + wq;
        int gwi = b * (Hn * WPR) + (r0 + i2) * WPR + wq;
#pragma unroll
        for (int p = 0; p < 8; p++)
            bp2[p * PW + gwi] = s_mov[1][p][rw];
    }
}

// ---------------------------------------------------------------------------
// Decompress: thread = 4 px x 20 channels (coalesced float4 stores).
// ---------------------------------------------------------------------------
__global__ void __launch_bounds__(256) k_decompress(
    const unsigned int* __restrict__ bp2, unsigned int* __restrict__ out)
{
    int t  = blockIdx.x * 256 + threadIdx.x;     // NPIX/4 threads
    int w  = t >> 3;                             // plane word index
    int kk = (t & 7) * 4;                        // bit offset of this quad
    unsigned p0 = bp2[0*PW + w], p1 = bp2[1*PW + w];
    unsigned p2 = bp2[2*PW + w], p3 = bp2[3*PW + w];
    unsigned p4 = bp2[4*PW + w], p5 = bp2[5*PW + w];
    unsigned p6 = bp2[6*PW + w], p7 = bp2[7*PW + w];

    int b   = t >> 16;                           // (t*4)/HW
    int off = (t * 4) & (HW - 1);
    unsigned* ob = out + (size_t)b * 20 * HW + off;
    const unsigned ONE = 0x3f800000u;

#pragma unroll
    for (int ch = 0; ch < 14; ch++) {
        unsigned mc = eq_elem4(p0, p1, p2, p3, ch) >> kk;
        uint4 v;
        v.x = (mc & 1) ? ONE : 0u;
        v.y = (mc & 2) ? ONE : 0u;
        v.z = (mc & 4) ? ONE : 0u;
        v.w = (mc & 8) ? ONE : 0u;
        *reinterpret_cast<uint4*>(ob + (size_t)ch * HW) = v;
    }
    {
        uint4 v;
#pragma unroll
        for (int q = 0; q < 4; q++) {
            unsigned b0 = (p4 >> (kk + q)) & 1, b1 = (p5 >> (kk + q)) & 1,
                     b2 = (p6 >> (kk + q)) & 1;
            (&v.x)[q] = b2 ? 0x40800000u
                      : (b1 ? (b0 ? 0x40400000u : 0x40000000u)
                            : (b0 ? 0x3f800000u : 0u));
        }
        *reinterpret_cast<uint4*>(ob + (size_t)14 * HW) = v;
    }
    {
        unsigned mg = p7 >> kk;
        uint4 v;
        v.x = (mg & 1) ? ONE : 0u;
        v.y = (mg & 2) ? ONE : 0u;
        v.z = (mg & 4) ? ONE : 0u;
        v.w = (mg & 8) ? ONE : 0u;
        *reinterpret_cast<uint4*>(ob + (size_t)15 * HW) = v;
    }
    uint4 z = make_uint4(0u, 0u, 0u, 0u);
#pragma unroll
    for (int ch = 16; ch < 20; ch++)
        *reinterpret_cast<uint4*>(ob + (size_t)ch * HW) = z;
}

// ---------------------------------------------------------------------------
extern "C" void kernel_launch(void* const* d_in, const int* in_sizes, int n_in,
                              void* d_out, int out_size)
{
    int wi = 0, ri = 1;
    if (n_in >= 2 && in_sizes[0] < in_sizes[1]) { wi = 1; ri = 0; }
    const float* world = (const float*)d_in[wi];
    const float* rnd   = (const float*)d_in[ri];
    unsigned* out = (unsigned*)d_out;

    unsigned int *bp, *bp2;
    cudaGetSymbolAddress((void**)&bp,  g_bp);
    cudaGetSymbolAddress((void**)&bp2, g_bp2);

    k_compress<<<(NPIX/4) / 256, 256>>>(world, rnd, bp);
    k_passes<<<NBLK, NTH>>>(bp, bp2);
    k_decompress<<<(NPIX/4) / 256, 256>>>(bp2, out);
}